// round 15
// baseline (speedup 1.0000x reference)
#include <cuda_runtime.h>
#include <cuda_bf16.h>
#include <cstdint>
#include <cstddef>

#define TS 1024
#define BB 64
#define HH 1024
#define G4 4096
#define K3 3072

__device__ float g_xproj[(size_t)TS * BB * G4];
__device__ unsigned g_count = 0;
__device__ unsigned g_gen = 0;
__device__ __align__(256) __nv_bfloat16 g_xc[(size_t)TS * BB * K3];  // [row][hi|hi|lo]
__device__ __align__(256) __nv_bfloat16 g_wc[(size_t)G4 * K3];       // [row][hi|lo|hi]
__device__ __align__(256) __nv_bfloat16 g_hh[3][2][BB * HH];         // [buf][hi/lo][b*HH+j]

__device__ __forceinline__ float sigf(float x) { return 1.0f / (1.0f + __expf(-x)); }

__device__ __forceinline__ uint32_t su32(const void* p) {
    uint32_t a;
    asm("{ .reg .u64 t; cvta.to.shared.u64 t, %1; cvt.u32.u64 %0, t; }" : "=r"(a) : "l"(p));
    return a;
}

#define CPA16(dst, src) asm volatile("cp.async.cg.shared.global [%0], [%1], 16;" :: "r"(dst), "l"(src))
#define CPA_COMMIT() asm volatile("cp.async.commit_group;" ::: "memory")
#define CPA_WAIT1() asm volatile("cp.async.wait_group 1;" ::: "memory")
#define CPA_WAIT2() asm volatile("cp.async.wait_group 2;" ::: "memory")

#define LDSM4(r, addr) asm volatile( \
    "ldmatrix.sync.aligned.m8n8.x4.shared.b16 {%0,%1,%2,%3}, [%4];" \
    : "=r"((r)[0]), "=r"((r)[1]), "=r"((r)[2]), "=r"((r)[3]) : "r"(addr))

#define MMA16816(d, a, b0, b1) asm volatile( \
    "mma.sync.aligned.m16n8k16.row.col.f32.bf16.bf16.f32 " \
    "{%0,%1,%2,%3}, {%4,%5,%6,%7}, {%8,%9}, {%0,%1,%2,%3};" \
    : "+f"((d)[0]), "+f"((d)[1]), "+f"((d)[2]), "+f"((d)[3]) \
    : "r"((a)[0]), "r"((a)[1]), "r"((a)[2]), "r"((a)[3]), "r"(b0), "r"(b1))

// ======== conversion: fp32 -> MISMATCHED concat (R10, proven) ========
__global__ __launch_bounds__(256) void cvt_x_kernel(const float* __restrict__ src) {
    const size_t i = (size_t)blockIdx.x * 256 + threadIdx.x;
    const float4 v = ((const float4*)src)[i];
    const size_t e = i * 4;
    __nv_bfloat16* d = g_xc + (e >> 10) * K3 + (e & 1023);
    const float f[4] = { v.x, v.y, v.z, v.w };
    __nv_bfloat16 h[4], l[4];
#pragma unroll
    for (int j = 0; j < 4; j++) {
        h[j] = __float2bfloat16(f[j]);
        l[j] = __float2bfloat16(f[j] - __bfloat162float(h[j]));
    }
    *(__nv_bfloat162*)(d)        = __nv_bfloat162(h[0], h[1]);
    *(__nv_bfloat162*)(d + 2)    = __nv_bfloat162(h[2], h[3]);
    *(__nv_bfloat162*)(d + 1024) = __nv_bfloat162(h[0], h[1]);
    *(__nv_bfloat162*)(d + 1026) = __nv_bfloat162(h[2], h[3]);
    *(__nv_bfloat162*)(d + 2048) = __nv_bfloat162(l[0], l[1]);
    *(__nv_bfloat162*)(d + 2050) = __nv_bfloat162(l[2], l[3]);
}
__global__ __launch_bounds__(256) void cvt_w_kernel(const float* __restrict__ src) {
    const size_t i = (size_t)blockIdx.x * 256 + threadIdx.x;
    const float4 v = ((const float4*)src)[i];
    const size_t e = i * 4;
    __nv_bfloat16* d = g_wc + (e >> 10) * K3 + (e & 1023);
    const float f[4] = { v.x, v.y, v.z, v.w };
    __nv_bfloat16 h[4], l[4];
#pragma unroll
    for (int j = 0; j < 4; j++) {
        h[j] = __float2bfloat16(f[j]);
        l[j] = __float2bfloat16(f[j] - __bfloat162float(h[j]));
    }
    *(__nv_bfloat162*)(d)        = __nv_bfloat162(h[0], h[1]);
    *(__nv_bfloat162*)(d + 2)    = __nv_bfloat162(h[2], h[3]);
    *(__nv_bfloat162*)(d + 1024) = __nv_bfloat162(l[0], l[1]);
    *(__nv_bfloat162*)(d + 1026) = __nv_bfloat162(l[2], l[3]);
    *(__nv_bfloat162*)(d + 2048) = __nv_bfloat162(h[0], h[1]);
    *(__nv_bfloat162*)(d + 2050) = __nv_bfloat162(h[2], h[3]);
}

// ===================== Kernel 1: x_proj GEMM, 3-stage pipeline ================
// dyn smem: As 3x10240 | Bs 3x10240 | bias 512 = 61952 B. ONE sync per k-iter.
#define XST 10240
#define XSMT (6 * XST + 512)

__global__ __launch_bounds__(256) void xproj_mma_kernel(
    const float* __restrict__ bih, const float* __restrict__ bhh)
{
    extern __shared__ char xsm[];
    char* As = xsm;
    char* Bs = xsm + 3 * XST;
    float* bias_sm = (float*)(xsm + 6 * XST);

    const int tid = threadIdx.x, wid = tid >> 5, lane = tid & 31;
    const int n0 = blockIdx.x * 128, m0 = blockIdx.y * 128;
    const int wm = wid & 3, wn = wid >> 2;
    const uint32_t suA = su32(As), suB = su32(Bs);
    const __nv_bfloat16* Xc = g_xc;
    const __nv_bfloat16* Wc = g_wc;

    if (tid < 128) bias_sm[tid] = bih[n0 + tid] + bhh[n0 + tid];

    float c[2][8][4];
#pragma unroll
    for (int mf = 0; mf < 2; mf++)
#pragma unroll
        for (int nf = 0; nf < 8; nf++)
#pragma unroll
            for (int q = 0; q < 4; q++) c[mf][nf][q] = 0.f;

    auto load_stage = [&](int kt, int buf) {
#pragma unroll
        for (int u = 0; u < 2; u++) {
            const int idx = tid + 256 * u;
            const int row = idx >> 2, c4 = idx & 3;
            CPA16(suA + buf * XST + row * 80 + c4 * 16,
                  Xc + (size_t)(m0 + row) * K3 + kt * 32 + c4 * 8);
            CPA16(suB + buf * XST + row * 80 + c4 * 16,
                  Wc + (size_t)(n0 + row) * K3 + kt * 32 + c4 * 8);
        }
    };

    load_stage(0, 0); CPA_COMMIT();
    load_stage(1, 1); CPA_COMMIT();

    const int lrow = lane & 15;
    const int lkof = (lane >> 4) << 4;

    const int NKT = K3 / 32;
    for (int kt = 0; kt < NKT; ++kt) {
        const int buf = kt % 3;
        CPA_WAIT1();
        __syncthreads();
        if (kt + 2 < NKT) load_stage(kt + 2, (kt + 2) % 3);
        CPA_COMMIT();
        const uint32_t Ab = suA + buf * XST;
        const uint32_t Bb = suB + buf * XST;
#pragma unroll
        for (int s = 0; s < 2; s++) {
            const int kby = s * 32 + lkof;
            uint32_t a0[4], a1[4];
            LDSM4(a0, Ab + (wm * 32 + lrow) * 80 + kby);
            LDSM4(a1, Ab + (wm * 32 + 16 + lrow) * 80 + kby);
            uint32_t bf[4][4];
#pragma unroll
            for (int n4 = 0; n4 < 4; n4++)
                LDSM4(bf[n4], Bb + (wn * 64 + n4 * 16 + lrow) * 80 + kby);
#pragma unroll
            for (int n4 = 0; n4 < 4; n4++) {
                MMA16816(c[0][n4 * 2],     a0, bf[n4][0], bf[n4][2]);
                MMA16816(c[0][n4 * 2 + 1], a0, bf[n4][1], bf[n4][3]);
                MMA16816(c[1][n4 * 2],     a1, bf[n4][0], bf[n4][2]);
                MMA16816(c[1][n4 * 2 + 1], a1, bf[n4][1], bf[n4][3]);
            }
        }
    }

    const int rbase = m0 + wm * 32 + (lane >> 2);
    const int cloc = wn * 64 + (lane & 3) * 2;
#pragma unroll
    for (int mf = 0; mf < 2; mf++) {
#pragma unroll
        for (int nf = 0; nf < 8; nf++) {
            const int col = cloc + nf * 8;
            const float b0 = bias_sm[col], b1 = bias_sm[col + 1];
            float* p0 = g_xproj + (size_t)(rbase + mf * 16) * G4 + n0 + col;
            float* p1 = p0 + 8 * G4;
            *(float2*)p0 = make_float2(c[mf][nf][0] + b0, c[mf][nf][1] + b1);
            *(float2*)p1 = make_float2(c[mf][nf][2] + b0, c[mf][nf][3] + b1);
        }
    }
}

// ===================== split grid barrier =====================
__device__ __forceinline__ unsigned gb_arrive()
{
    __syncthreads();
    unsigned gen = 0;
    if (threadIdx.x == 0) {
        __threadfence();
        gen = *(volatile unsigned*)&g_gen;
        atomicAdd(&g_count, 1u);
    }
    return gen;
}
__device__ __forceinline__ void gb_wait(unsigned gen)
{
    if (threadIdx.x == 0) {
        if (blockIdx.x == 0) {
            while (*(volatile unsigned*)&g_count != gridDim.x) { __nanosleep(32); }
            g_count = 0;
            __threadfence();
            atomicAdd(&g_gen, 1u);
        } else {
            while (*(volatile unsigned*)&g_gen == gen) { }
        }
        __threadfence();
    }
    __syncthreads();
}

// ===================== Kernel 2: tensor-core recurrence ======================
// 128 CTAs x 512 threads, K-split 16 warps, 4-stage A pipeline (lookahead 3),
// split arrive/wait barrier with xp prefetch in the gap.
#define WROW 2064
#define SM_WH 0
#define SM_WL 66048
#define SM_A  132096               // 8 groups x 4 stages x 2560 = 81920
#define SM_C  214016               // 2 x 64 x 33 floats = 16896
#define SMT   230912

__global__ __launch_bounds__(512, 1) void lstm_rec_tc(
    const float* __restrict__ Whh, const float* __restrict__ h0,
    const float* __restrict__ c0, float* __restrict__ out, int out_size)
{
    extern __shared__ char sm[];
    const uint32_t smb = su32(sm);

    const int tid = threadIdx.x, lane = tid & 31, wid = tid >> 5;
    const int j0 = blockIdx.x * 8;
    const int km = wid >> 3;
    const int wm = wid & 3, wn = (wid >> 2) & 1;
    const int grp8 = km * 4 + wm;
    const int lrow = lane & 15, lkof = (lane >> 4) << 4;
    const int lseg = (lane >> 4) * 32;
    const int b0_ = tid >> 3, jl = tid & 7;

    // ---- W_hh slice -> smem hi/lo (once): 32 rows x 1024 ----
    {
        const int n = tid >> 4, seg = tid & 15;
        const float* src = Whh + (size_t)((n >> 3) * HH + j0 + (n & 7)) * HH + seg * 64;
        __nv_bfloat16* dh = (__nv_bfloat16*)(sm + SM_WH + n * WROW) + seg * 64;
        __nv_bfloat16* dl = (__nv_bfloat16*)(sm + SM_WL + n * WROW) + seg * 64;
        for (int q = 0; q < 16; q++) {
            const float4 v = *(const float4*)&src[q * 4];
            const float f[4] = { v.x, v.y, v.z, v.w };
            __nv_bfloat16 h4[4], l4[4];
#pragma unroll
            for (int j = 0; j < 4; j++) {
                h4[j] = __float2bfloat16(f[j]);
                l4[j] = __float2bfloat16(f[j] - __bfloat162float(h4[j]));
            }
            *(__nv_bfloat162*)(dh + q * 4)     = __nv_bfloat162(h4[0], h4[1]);
            *(__nv_bfloat162*)(dh + q * 4 + 2) = __nv_bfloat162(h4[2], h4[3]);
            *(__nv_bfloat162*)(dl + q * 4)     = __nv_bfloat162(l4[0], l4[1]);
            *(__nv_bfloat162*)(dl + q * 4 + 2) = __nv_bfloat162(l4[2], l4[3]);
        }
    }
    // ---- h0 split -> g_hh[0] (one elem/thread) ----
    {
        const size_t e = (size_t)blockIdx.x * 512 + tid;
        const float v = h0[e];
        const __nv_bfloat16 hh = __float2bfloat16(v);
        g_hh[0][0][e] = hh;
        g_hh[0][1][e] = __float2bfloat16(v - __bfloat162float(hh));
    }
    float c_reg = c0[(size_t)b0_ * HH + j0 + jl];
    float hlast = 0.f;

    const int hT = TS * BB * HH;
    const uint32_t abase = smb + SM_A + grp8 * 10240 + wn * 1280 + lrow * 80 + lseg;
    const uint32_t cbase = smb + SM_A + grp8 * 10240 + lrow * 80;
    const uint32_t Bhr = smb + SM_WH + (wn * 16 + lrow) * WROW + km * 1024;
    const uint32_t Blr = smb + SM_WL + (wn * 16 + lrow) * WROW + km * 1024;
    float* Csm0 = (float*)(sm + SM_C);
    float* Csm1 = Csm0 + 64 * 33;
    float* Cmine = km ? Csm1 : Csm0;

    float xpv[4];
    auto xp_load = [&](int tt) {
        const float* xpr = g_xproj + ((size_t)tt * BB + b0_) * G4;
#pragma unroll
        for (int g = 0; g < 4; g++)
            xpv[g] = __ldcs(&xpr[g * HH + j0 + jl]);
    };

    unsigned genv = gb_arrive();
    xp_load(0);

    for (int t = 0; t < TS; ++t) {
        gb_wait(genv);                                   // h[t] published

        const int rb = t % 3, wb = (t + 1) % 3;
        const char* Asrc = (const char*)g_hh[rb][wn];    // wn0: hi, wn1: lo
        const size_t sof = (size_t)(wm * 16 + lrow) * 2048 + km * 1024 + lseg;

        float c[6][4];
#pragma unroll
        for (int i = 0; i < 6; i++)
#pragma unroll
            for (int q = 0; q < 4; q++) c[i][q] = 0.f;

        // prologue: stages 0..2
#pragma unroll
        for (int s = 0; s < 3; s++) {
            const char* sp = Asrc + sof + (size_t)s * 64;
            CPA16(abase + s * 2560, sp);
            CPA16(abase + s * 2560 + 16, sp + 16);
            CPA_COMMIT();
        }

        for (int kt = 0; kt < 16; ++kt) {
            CPA_WAIT2();
            asm volatile("bar.sync %0, 64;" :: "r"(1 + grp8) : "memory");
            if (kt + 3 < 16) {
                const uint32_t d = abase + ((kt + 3) & 3) * 2560;
                const char* s = Asrc + sof + (size_t)(kt + 3) * 64;
                CPA16(d, s); CPA16(d + 16, s + 16);
            }
            CPA_COMMIT();

            const uint32_t Ahs = cbase + (kt & 3) * 2560;
            const uint32_t Als = Ahs + 1280;
#pragma unroll
            for (int s = 0; s < 2; s++) {
                const int kby = s * 32 + lkof;
                const int kwb = kt * 64 + kby;
                uint32_t ah[4], al[4], bh[4], bl[4];
                LDSM4(ah, Ahs + kby);
                LDSM4(al, Als + kby);
                LDSM4(bh, Bhr + kwb);
                LDSM4(bl, Blr + kwb);
                MMA16816(c[0], ah, bh[0], bh[2]);
                MMA16816(c[1], ah, bh[1], bh[3]);
                MMA16816(c[2], ah, bl[0], bl[2]);
                MMA16816(c[3], ah, bl[1], bl[3]);
                MMA16816(c[4], al, bh[0], bh[2]);
                MMA16816(c[5], al, bh[1], bh[3]);
            }
        }

        // ---- merge streams -> C region for this km ----
        {
            const int r0 = wm * 16 + (lane >> 2);
            const int cb = wn * 16 + (lane & 3) * 2;
#pragma unroll
            for (int nf = 0; nf < 2; nf++) {
                Cmine[r0 * 33 + cb + nf * 8]           = c[nf][0] + c[nf + 2][0] + c[nf + 4][0];
                Cmine[r0 * 33 + cb + nf * 8 + 1]       = c[nf][1] + c[nf + 2][1] + c[nf + 4][1];
                Cmine[(r0 + 8) * 33 + cb + nf * 8]     = c[nf][2] + c[nf + 2][2] + c[nf + 4][2];
                Cmine[(r0 + 8) * 33 + cb + nf * 8 + 1] = c[nf][3] + c[nf + 2][3] + c[nf + 4][3];
            }
        }
        __syncthreads();

        // ---- LSTM cell ----
        {
            const int b = b0_;
            const float Gi = Csm0[b * 33 + jl]      + Csm1[b * 33 + jl]      + xpv[0];
            const float Gf = Csm0[b * 33 + 8 + jl]  + Csm1[b * 33 + 8 + jl]  + xpv[1];
            const float Gg = Csm0[b * 33 + 16 + jl] + Csm1[b * 33 + 16 + jl] + xpv[2];
            const float Go = Csm0[b * 33 + 24 + jl] + Csm1[b * 33 + 24 + jl] + xpv[3];
            const float iv = sigf(Gi), fv = sigf(Gf);
            const float gv = tanhf(Gg), ov = sigf(Go);
            const float cn = fmaf(fv, c_reg, iv * gv);
            c_reg = cn;
            const float hv = ov * tanhf(cn);
            hlast = hv;
            out[((size_t)t * BB + b) * HH + j0 + jl] = hv;
            const __nv_bfloat16 hh = __float2bfloat16(hv);
            g_hh[wb][0][b * HH + j0 + jl] = hh;
            g_hh[wb][1][b * HH + j0 + jl] =
                __float2bfloat16(hv - __bfloat162float(hh));
        }

        genv = gb_arrive();                  // publish h[t+1]
        if (t + 1 < TS) xp_load(t + 1);      // overlap with barrier wait
    }
    gb_wait(genv);                           // restore barrier state for replay

    if (out_size >= hT + 2 * BB * HH) {
        out[hT + (size_t)b0_ * HH + j0 + jl] = hlast;
        out[hT + BB * HH + (size_t)b0_ * HH + j0 + jl] = c_reg;
    }
}

extern "C" void kernel_launch(void* const* d_in, const int* in_sizes, int n_in,
                              void* d_out, int out_size)
{
    const float* x   = (const float*)d_in[0];
    const float* Wih = (const float*)d_in[1];
    const float* Whh = (const float*)d_in[2];
    const float* bih = (const float*)d_in[3];
    const float* bhh = (const float*)d_in[4];
    const float* h0  = (const float*)d_in[5];
    const float* c0  = (const float*)d_in[6];
    float* out = (float*)d_out;

    static bool attr_set = false;
    if (!attr_set) {
        cudaFuncSetAttribute(lstm_rec_tc,
                             cudaFuncAttributeMaxDynamicSharedMemorySize, SMT);
        cudaFuncSetAttribute(xproj_mma_kernel,
                             cudaFuncAttributeMaxDynamicSharedMemorySize, XSMT);
        attr_set = true;
    }

    cvt_x_kernel<<<(TS * BB * HH / 4) / 256, 256>>>(x);
    cvt_w_kernel<<<(G4 * HH / 4) / 256, 256>>>(Wih);
    dim3 g1(G4 / 128, (TS * BB) / 128);
    xproj_mma_kernel<<<g1, 256, XSMT>>>(bih, bhh);
    lstm_rec_tc<<<128, 512, SMT>>>(Whh, h0, c0, out, out_size);
}

// round 17
// speedup vs baseline: 1.0320x; 1.0320x over previous
#include <cuda_runtime.h>
#include <cuda_bf16.h>
#include <cstdint>
#include <cstddef>

#define TS 1024
#define BB 64
#define HH 1024
#define G4 4096
#define K3 3072

__device__ float g_xproj[(size_t)TS * BB * G4];
__device__ unsigned g_count = 0;
__device__ __align__(256) __nv_bfloat16 g_xc[(size_t)TS * BB * K3];  // [row][hi|hi|lo]
__device__ __align__(256) __nv_bfloat16 g_wc[(size_t)G4 * K3];       // [row][hi|lo|hi]
__device__ __align__(256) __nv_bfloat16 g_hh[3][2][BB * HH];         // [buf][hi/lo][b*HH+j]

__device__ __forceinline__ float sigf(float x) { return 1.0f / (1.0f + __expf(-x)); }

__device__ __forceinline__ uint32_t su32(const void* p) {
    uint32_t a;
    asm("{ .reg .u64 t; cvta.to.shared.u64 t, %1; cvt.u32.u64 %0, t; }" : "=r"(a) : "l"(p));
    return a;
}

#define CPA16(dst, src) asm volatile("cp.async.cg.shared.global [%0], [%1], 16;" :: "r"(dst), "l"(src))
#define CPA_COMMIT() asm volatile("cp.async.commit_group;" ::: "memory")
#define CPA_WAIT1() asm volatile("cp.async.wait_group 1;" ::: "memory")
#define CPA_WAIT2() asm volatile("cp.async.wait_group 2;" ::: "memory")

#define LDSM4(r, addr) asm volatile( \
    "ldmatrix.sync.aligned.m8n8.x4.shared.b16 {%0,%1,%2,%3}, [%4];" \
    : "=r"((r)[0]), "=r"((r)[1]), "=r"((r)[2]), "=r"((r)[3]) : "r"(addr))

#define MMA16816(d, a, b0, b1) asm volatile( \
    "mma.sync.aligned.m16n8k16.row.col.f32.bf16.bf16.f32 " \
    "{%0,%1,%2,%3}, {%4,%5,%6,%7}, {%8,%9}, {%0,%1,%2,%3};" \
    : "+f"((d)[0]), "+f"((d)[1]), "+f"((d)[2]), "+f"((d)[3]) \
    : "r"((a)[0]), "r"((a)[1]), "r"((a)[2]), "r"((a)[3]), "r"(b0), "r"(b1))

// ======== conversion: fp32 -> MISMATCHED concat (R10, proven) ========
__global__ __launch_bounds__(256) void cvt_x_kernel(const float* __restrict__ src) {
    const size_t i = (size_t)blockIdx.x * 256 + threadIdx.x;
    const float4 v = ((const float4*)src)[i];
    const size_t e = i * 4;
    __nv_bfloat16* d = g_xc + (e >> 10) * K3 + (e & 1023);
    const float f[4] = { v.x, v.y, v.z, v.w };
    __nv_bfloat16 h[4], l[4];
#pragma unroll
    for (int j = 0; j < 4; j++) {
        h[j] = __float2bfloat16(f[j]);
        l[j] = __float2bfloat16(f[j] - __bfloat162float(h[j]));
    }
    *(__nv_bfloat162*)(d)        = __nv_bfloat162(h[0], h[1]);
    *(__nv_bfloat162*)(d + 2)    = __nv_bfloat162(h[2], h[3]);
    *(__nv_bfloat162*)(d + 1024) = __nv_bfloat162(h[0], h[1]);
    *(__nv_bfloat162*)(d + 1026) = __nv_bfloat162(h[2], h[3]);
    *(__nv_bfloat162*)(d + 2048) = __nv_bfloat162(l[0], l[1]);
    *(__nv_bfloat162*)(d + 2050) = __nv_bfloat162(l[2], l[3]);
}
__global__ __launch_bounds__(256) void cvt_w_kernel(const float* __restrict__ src) {
    const size_t i = (size_t)blockIdx.x * 256 + threadIdx.x;
    const float4 v = ((const float4*)src)[i];
    const size_t e = i * 4;
    __nv_bfloat16* d = g_wc + (e >> 10) * K3 + (e & 1023);
    const float f[4] = { v.x, v.y, v.z, v.w };
    __nv_bfloat16 h[4], l[4];
#pragma unroll
    for (int j = 0; j < 4; j++) {
        h[j] = __float2bfloat16(f[j]);
        l[j] = __float2bfloat16(f[j] - __bfloat162float(h[j]));
    }
    *(__nv_bfloat162*)(d)        = __nv_bfloat162(h[0], h[1]);
    *(__nv_bfloat162*)(d + 2)    = __nv_bfloat162(h[2], h[3]);
    *(__nv_bfloat162*)(d + 1024) = __nv_bfloat162(l[0], l[1]);
    *(__nv_bfloat162*)(d + 1026) = __nv_bfloat162(l[2], l[3]);
    *(__nv_bfloat162*)(d + 2048) = __nv_bfloat162(h[0], h[1]);
    *(__nv_bfloat162*)(d + 2050) = __nv_bfloat162(h[2], h[3]);
}

// ===================== Kernel 1: x_proj GEMM, M128 x N256, 512 thr ===========
// 3-stage pipeline; warp tile 32x64 (16 warps = 4 wm x 4 wn).
#define XST_A 10240
#define XST_B 20480
#define XOFF_B (3 * XST_A)
#define XOFF_BIAS (3 * XST_A + 3 * XST_B)
#define XSMT (XOFF_BIAS + 1024)

__global__ __launch_bounds__(512) void xproj_mma_kernel(
    const float* __restrict__ bih, const float* __restrict__ bhh)
{
    extern __shared__ char xsm[];
    float* bias_sm = (float*)(xsm + XOFF_BIAS);

    const int tid = threadIdx.x, wid = tid >> 5, lane = tid & 31;
    const int n0 = blockIdx.x * 256, m0 = blockIdx.y * 128;
    const int wm = wid & 3, wn = wid >> 2;
    const uint32_t suA = su32(xsm), suB = su32(xsm + XOFF_B);
    const __nv_bfloat16* Xc = g_xc;
    const __nv_bfloat16* Wc = g_wc;

    if (tid < 256) bias_sm[tid] = bih[n0 + tid] + bhh[n0 + tid];

    float c[2][8][4];
#pragma unroll
    for (int mf = 0; mf < 2; mf++)
#pragma unroll
        for (int nf = 0; nf < 8; nf++)
#pragma unroll
            for (int q = 0; q < 4; q++) c[mf][nf][q] = 0.f;

    auto load_stage = [&](int kt, int buf) {
        {   // u = 0: A rows 0..127
            const int row = tid >> 2, c4 = tid & 3;
            CPA16(suA + buf * XST_A + row * 80 + c4 * 16,
                  Xc + (size_t)(m0 + row) * K3 + kt * 32 + c4 * 8);
        }
#pragma unroll
        for (int u = 1; u < 3; u++) {   // B rows 0..255
            const int j = tid + 512 * u - 512;
            const int row = j >> 2, c4 = j & 3;
            CPA16(suB + buf * XST_B + row * 80 + c4 * 16,
                  Wc + (size_t)(n0 + row) * K3 + kt * 32 + c4 * 8);
        }
    };

    load_stage(0, 0); CPA_COMMIT();
    load_stage(1, 1); CPA_COMMIT();

    const int lrow = lane & 15;
    const int lkof = (lane >> 4) << 4;

    const int NKT = K3 / 32;
    for (int kt = 0; kt < NKT; ++kt) {
        const int buf = kt % 3;
        CPA_WAIT1();
        __syncthreads();
        if (kt + 2 < NKT) load_stage(kt + 2, (kt + 2) % 3);
        CPA_COMMIT();
        const uint32_t Ab = suA + buf * XST_A;
        const uint32_t Bb = suB + buf * XST_B;
#pragma unroll
        for (int s = 0; s < 2; s++) {
            const int kby = s * 32 + lkof;
            uint32_t a0[4], a1[4];
            LDSM4(a0, Ab + (wm * 32 + lrow) * 80 + kby);
            LDSM4(a1, Ab + (wm * 32 + 16 + lrow) * 80 + kby);
            uint32_t bf[4][4];
#pragma unroll
            for (int n4 = 0; n4 < 4; n4++)
                LDSM4(bf[n4], Bb + (wn * 64 + n4 * 16 + lrow) * 80 + kby);
#pragma unroll
            for (int n4 = 0; n4 < 4; n4++) {
                MMA16816(c[0][n4 * 2],     a0, bf[n4][0], bf[n4][2]);
                MMA16816(c[0][n4 * 2 + 1], a0, bf[n4][1], bf[n4][3]);
                MMA16816(c[1][n4 * 2],     a1, bf[n4][0], bf[n4][2]);
                MMA16816(c[1][n4 * 2 + 1], a1, bf[n4][1], bf[n4][3]);
            }
        }
    }

    const int rbase = m0 + wm * 32 + (lane >> 2);
    const int cloc = wn * 64 + (lane & 3) * 2;
#pragma unroll
    for (int mf = 0; mf < 2; mf++) {
#pragma unroll
        for (int nf = 0; nf < 8; nf++) {
            const int col = cloc + nf * 8;
            const float b0 = bias_sm[col], b1 = bias_sm[col + 1];
            float* p0 = g_xproj + (size_t)(rbase + mf * 16) * G4 + n0 + col;
            float* p1 = p0 + 8 * G4;
            *(float2*)p0 = make_float2(c[mf][nf][0] + b0, c[mf][nf][1] + b1);
            *(float2*)p1 = make_float2(c[mf][nf][2] + b0, c[mf][nf][3] + b1);
        }
    }
}

// ===================== monotonic grid barrier =====================
__device__ __forceinline__ void gb_arrive()
{
    __syncthreads();
    if (threadIdx.x == 0) {
        __threadfence();
        atomicAdd(&g_count, 1u);
    }
}
__device__ __forceinline__ void gb_wait(unsigned target)
{
    if (threadIdx.x == 0) {
        while (*(volatile unsigned*)&g_count < target) { }
        __threadfence();
    }
    __syncthreads();
}

// ===================== Kernel 2: tensor-core recurrence (R15 body) ===========
// 128 CTAs x 512 threads, K-split 16 warps, 4-stage A pipeline, monotonic
// barrier with xp prefetch in the arrive/wait gap.
#define WROW 2064
#define SM_WH 0
#define SM_WL 66048
#define SM_A  132096               // 8 groups x 4 stages x 2560 = 81920
#define SM_C  214016               // 2 x 64 x 33 floats = 16896
#define SMT   230912

__global__ __launch_bounds__(512, 1) void lstm_rec_tc(
    const float* __restrict__ Whh, const float* __restrict__ h0,
    const float* __restrict__ c0, float* __restrict__ out, int out_size)
{
    extern __shared__ char sm[];
    const uint32_t smb = su32(sm);

    const int tid = threadIdx.x, lane = tid & 31, wid = tid >> 5;
    const int j0 = blockIdx.x * 8;
    const int km = wid >> 3;
    const int wm = wid & 3, wn = (wid >> 2) & 1;
    const int grp8 = km * 4 + wm;
    const int lrow = lane & 15, lkof = (lane >> 4) << 4;
    const int lseg = (lane >> 4) * 32;
    const int b0_ = tid >> 3, jl = tid & 7;
    const unsigned NB = gridDim.x;

    // ---- W_hh slice -> smem hi/lo (once): 32 rows x 1024 ----
    {
        const int n = tid >> 4, seg = tid & 15;
        const float* src = Whh + (size_t)((n >> 3) * HH + j0 + (n & 7)) * HH + seg * 64;
        __nv_bfloat16* dh = (__nv_bfloat16*)(sm + SM_WH + n * WROW) + seg * 64;
        __nv_bfloat16* dl = (__nv_bfloat16*)(sm + SM_WL + n * WROW) + seg * 64;
        for (int q = 0; q < 16; q++) {
            const float4 v = *(const float4*)&src[q * 4];
            const float f[4] = { v.x, v.y, v.z, v.w };
            __nv_bfloat16 h4[4], l4[4];
#pragma unroll
            for (int j = 0; j < 4; j++) {
                h4[j] = __float2bfloat16(f[j]);
                l4[j] = __float2bfloat16(f[j] - __bfloat162float(h4[j]));
            }
            *(__nv_bfloat162*)(dh + q * 4)     = __nv_bfloat162(h4[0], h4[1]);
            *(__nv_bfloat162*)(dh + q * 4 + 2) = __nv_bfloat162(h4[2], h4[3]);
            *(__nv_bfloat162*)(dl + q * 4)     = __nv_bfloat162(l4[0], l4[1]);
            *(__nv_bfloat162*)(dl + q * 4 + 2) = __nv_bfloat162(l4[2], l4[3]);
        }
    }
    // ---- h0 split -> g_hh[0] (one elem/thread) ----
    {
        const size_t e = (size_t)blockIdx.x * 512 + tid;
        const float v = h0[e];
        const __nv_bfloat16 hh = __float2bfloat16(v);
        g_hh[0][0][e] = hh;
        g_hh[0][1][e] = __float2bfloat16(v - __bfloat162float(hh));
    }
    float c_reg = c0[(size_t)b0_ * HH + j0 + jl];
    float hlast = 0.f;

    const int hT = TS * BB * HH;
    const uint32_t abase = smb + SM_A + grp8 * 10240 + wn * 1280 + lrow * 80 + lseg;
    const uint32_t cbase = smb + SM_A + grp8 * 10240 + lrow * 80;
    const uint32_t Bhr = smb + SM_WH + (wn * 16 + lrow) * WROW + km * 1024;
    const uint32_t Blr = smb + SM_WL + (wn * 16 + lrow) * WROW + km * 1024;
    float* Csm0 = (float*)(sm + SM_C);
    float* Csm1 = Csm0 + 64 * 33;
    float* Cmine = km ? Csm1 : Csm0;

    float xpv[4];
    auto xp_load = [&](int tt) {
        const float* xpr = g_xproj + ((size_t)tt * BB + b0_) * G4;
#pragma unroll
        for (int g = 0; g < 4; g++)
            xpv[g] = __ldcs(&xpr[g * HH + j0 + jl]);
    };

    gb_arrive();
    xp_load(0);

    for (int t = 0; t < TS; ++t) {
        gb_wait((unsigned)(t + 1) * NB);                 // h[t] published

        const int rb = t % 3, wb = (t + 1) % 3;
        const char* Asrc = (const char*)g_hh[rb][wn];    // wn0: hi, wn1: lo
        const size_t sof = (size_t)(wm * 16 + lrow) * 2048 + km * 1024 + lseg;

        float c[6][4];
#pragma unroll
        for (int i = 0; i < 6; i++)
#pragma unroll
            for (int q = 0; q < 4; q++) c[i][q] = 0.f;

        // prologue: stages 0..2
#pragma unroll
        for (int s = 0; s < 3; s++) {
            const char* sp = Asrc + sof + (size_t)s * 64;
            CPA16(abase + s * 2560, sp);
            CPA16(abase + s * 2560 + 16, sp + 16);
            CPA_COMMIT();
        }

        for (int kt = 0; kt < 16; ++kt) {
            CPA_WAIT2();
            asm volatile("bar.sync %0, 64;" :: "r"(1 + grp8) : "memory");
            if (kt + 3 < 16) {
                const uint32_t d = abase + ((kt + 3) & 3) * 2560;
                const char* s = Asrc + sof + (size_t)(kt + 3) * 64;
                CPA16(d, s); CPA16(d + 16, s + 16);
            }
            CPA_COMMIT();

            const uint32_t Ahs = cbase + (kt & 3) * 2560;
            const uint32_t Als = Ahs + 1280;
#pragma unroll
            for (int s = 0; s < 2; s++) {
                const int kby = s * 32 + lkof;
                const int kwb = kt * 64 + kby;
                uint32_t ah[4], al[4], bh[4], bl[4];
                LDSM4(ah, Ahs + kby);
                LDSM4(al, Als + kby);
                LDSM4(bh, Bhr + kwb);
                LDSM4(bl, Blr + kwb);
                MMA16816(c[0], ah, bh[0], bh[2]);
                MMA16816(c[1], ah, bh[1], bh[3]);
                MMA16816(c[2], ah, bl[0], bl[2]);
                MMA16816(c[3], ah, bl[1], bl[3]);
                MMA16816(c[4], al, bh[0], bh[2]);
                MMA16816(c[5], al, bh[1], bh[3]);
            }
        }

        // ---- merge streams -> C region for this km ----
        {
            const int r0 = wm * 16 + (lane >> 2);
            const int cb = wn * 16 + (lane & 3) * 2;
#pragma unroll
            for (int nf = 0; nf < 2; nf++) {
                Cmine[r0 * 33 + cb + nf * 8]           = c[nf][0] + c[nf + 2][0] + c[nf + 4][0];
                Cmine[r0 * 33 + cb + nf * 8 + 1]       = c[nf][1] + c[nf + 2][1] + c[nf + 4][1];
                Cmine[(r0 + 8) * 33 + cb + nf * 8]     = c[nf][2] + c[nf + 2][2] + c[nf + 4][2];
                Cmine[(r0 + 8) * 33 + cb + nf * 8 + 1] = c[nf][3] + c[nf + 2][3] + c[nf + 4][3];
            }
        }
        __syncthreads();

        // ---- LSTM cell ----
        {
            const int b = b0_;
            const float Gi = Csm0[b * 33 + jl]      + Csm1[b * 33 + jl]      + xpv[0];
            const float Gf = Csm0[b * 33 + 8 + jl]  + Csm1[b * 33 + 8 + jl]  + xpv[1];
            const float Gg = Csm0[b * 33 + 16 + jl] + Csm1[b * 33 + 16 + jl] + xpv[2];
            const float Go = Csm0[b * 33 + 24 + jl] + Csm1[b * 33 + 24 + jl] + xpv[3];
            const float iv = sigf(Gi), fv = sigf(Gf);
            const float gv = tanhf(Gg), ov = sigf(Go);
            const float cn = fmaf(fv, c_reg, iv * gv);
            c_reg = cn;
            const float hv = ov * tanhf(cn);
            hlast = hv;
            out[((size_t)t * BB + b) * HH + j0 + jl] = hv;
            const __nv_bfloat16 hh = __float2bfloat16(hv);
            g_hh[wb][0][b * HH + j0 + jl] = hh;
            g_hh[wb][1][b * HH + j0 + jl] =
                __float2bfloat16(hv - __bfloat162float(hh));
        }

        gb_arrive();                         // publish h[t+1]
        if (t + 1 < TS) xp_load(t + 1);      // overlap with barrier wait
    }

    // ---- reset counter for graph replay (block 0 only; others just exit) ----
    if (blockIdx.x == 0 && threadIdx.x == 0) {
        while (*(volatile unsigned*)&g_count < (unsigned)(TS + 1) * NB) { }
        g_count = 0;
        __threadfence();
    }

    if (out_size >= hT + 2 * BB * HH) {
        out[hT + (size_t)b0_ * HH + j0 + jl] = hlast;
        out[hT + BB * HH + (size_t)b0_ * HH + j0 + jl] = c_reg;
    }
}

extern "C" void kernel_launch(void* const* d_in, const int* in_sizes, int n_in,
                              void* d_out, int out_size)
{
    const float* x   = (const float*)d_in[0];
    const float* Wih = (const float*)d_in[1];
    const float* Whh = (const float*)d_in[2];
    const float* bih = (const float*)d_in[3];
    const float* bhh = (const float*)d_in[4];
    const float* h0  = (const float*)d_in[5];
    const float* c0  = (const float*)d_in[6];
    float* out = (float*)d_out;

    static bool attr_set = false;
    if (!attr_set) {
        cudaFuncSetAttribute(lstm_rec_tc,
                             cudaFuncAttributeMaxDynamicSharedMemorySize, SMT);
        cudaFuncSetAttribute(xproj_mma_kernel,
                             cudaFuncAttributeMaxDynamicSharedMemorySize, XSMT);
        attr_set = true;
    }

    cvt_x_kernel<<<(TS * BB * HH / 4) / 256, 256>>>(x);
    cvt_w_kernel<<<(G4 * HH / 4) / 256, 256>>>(Wih);
    dim3 g1(G4 / 256, (TS * BB) / 128);
    xproj_mma_kernel<<<g1, 512, XSMT>>>(bih, bhh);
    lstm_rec_tc<<<128, 512, SMT>>>(Whh, h0, c0, out, out_size);
}